// round 6
// baseline (speedup 1.0000x reference)
#include <cuda_runtime.h>
#include <cuda_bf16.h>
#include <cstdint>
#include <cstddef>

#define B_   32
#define S_   2048
#define D_   256
#define G3_  768

// gi scratch: [dir][b][s][768]  (402 MB, fully rewritten every call)
__device__ float g_gi[(size_t)2 * B_ * S_ * G3_];

// ---------------------------------------------------------------------------
// f32x2 packed-math helpers (sm_100+): two fp32 FMAs per issue slot.
// ---------------------------------------------------------------------------
__device__ __forceinline__ unsigned long long pack2(float x, float y) {
    unsigned long long v;
    asm("mov.b64 %0, {%1,%2};" : "=l"(v) : "f"(x), "f"(y));
    return v;
}
__device__ __forceinline__ float2 unpack2(unsigned long long v) {
    float2 f;
    asm("mov.b64 {%0,%1}, %2;" : "=f"(f.x), "=f"(f.y) : "l"(v));
    return f;
}
__device__ __forceinline__ void ffma2(unsigned long long& d,
                                      unsigned long long a,
                                      unsigned long long b) {
    asm("fma.rn.f32x2 %0, %1, %2, %0;" : "+l"(d) : "l"(a), "l"(b));
}

__device__ __forceinline__ uint32_t smem_u32(const void* p) {
    uint32_t a;
    asm("{ .reg .u64 t; cvta.to.shared.u64 t, %1; cvt.u32.u64 %0, t; }"
        : "=r"(a) : "l"(p));
    return a;
}

__device__ __forceinline__ float fast_sig(float x) {
    return __fdividef(1.f, 1.f + __expf(-x));
}
__device__ __forceinline__ float fast_tanh(float x) {
    return __fdividef(2.f, 1.f + __expf(-2.f * x)) - 1.f;
}

// ---------------------------------------------------------------------------
// Kernel 1: gi[dir][m][n] = V[m][:] . W_ih(dir)[n][:] + b_ih[n]
// M = 65536, N = 768, K = 256. 128x128x8 tile, 8x8 micro, FFMA2 microkernel.
// ---------------------------------------------------------------------------
__global__ __launch_bounds__(256, 2) void gi_gemm(
    const float* __restrict__ V,
    const float* __restrict__ Wf, const float* __restrict__ Wb,
    const float* __restrict__ bf, const float* __restrict__ bb)
{
    const int dir = blockIdx.z;
    const float* __restrict__ W   = dir ? Wb : Wf;
    const float* __restrict__ bih = dir ? bb : bf;
    const int m0 = blockIdx.x * 128;
    const int n0 = blockIdx.y * 128;

    __shared__ __align__(16) float As[2][8][132];   // 132: 16B-aligned rows, pad vs conflicts
    __shared__ __align__(16) float Bs[2][8][132];

    const int tid = threadIdx.x;
    const int lr  = tid >> 1;          // 0..127
    const int lk  = (tid & 1) * 4;     // 0 or 4

    const float* aptr = V + (size_t)(m0 + lr) * 256 + lk;
    const float* bptr = W + (size_t)(n0 + lr) * 256 + lk;

    const int tx = tid & 15;
    const int ty = tid >> 4;

    unsigned long long acc2[8][4];
#pragma unroll
    for (int i = 0; i < 8; i++)
#pragma unroll
        for (int j = 0; j < 4; j++) acc2[i][j] = 0ULL;

    float4 a = *(const float4*)aptr;
    float4 b = *(const float4*)bptr;
    As[0][lk + 0][lr] = a.x; As[0][lk + 1][lr] = a.y;
    As[0][lk + 2][lr] = a.z; As[0][lk + 3][lr] = a.w;
    Bs[0][lk + 0][lr] = b.x; Bs[0][lk + 1][lr] = b.y;
    Bs[0][lk + 2][lr] = b.z; Bs[0][lk + 3][lr] = b.w;
    __syncthreads();

    int cur = 0;
    for (int kt = 0; kt < 32; kt++) {
        if (kt < 31) {
            a = *(const float4*)(aptr + (kt + 1) * 8);
            b = *(const float4*)(bptr + (kt + 1) * 8);
        }
#pragma unroll
        for (int k = 0; k < 8; k++) {
            float4 a0 = *(const float4*)&As[cur][k][ty * 8];
            float4 a1 = *(const float4*)&As[cur][k][ty * 8 + 4];
            ulonglong2 bA = *(const ulonglong2*)&Bs[cur][k][tx * 8];
            ulonglong2 bB = *(const ulonglong2*)&Bs[cur][k][tx * 8 + 4];
            unsigned long long bv[4] = {bA.x, bA.y, bB.x, bB.y};
            unsigned long long av[8];
            av[0] = pack2(a0.x, a0.x); av[1] = pack2(a0.y, a0.y);
            av[2] = pack2(a0.z, a0.z); av[3] = pack2(a0.w, a0.w);
            av[4] = pack2(a1.x, a1.x); av[5] = pack2(a1.y, a1.y);
            av[6] = pack2(a1.z, a1.z); av[7] = pack2(a1.w, a1.w);
#pragma unroll
            for (int i = 0; i < 8; i++)
#pragma unroll
                for (int j = 0; j < 4; j++)
                    ffma2(acc2[i][j], av[i], bv[j]);
        }
        if (kt < 31) {
            const int nxt = cur ^ 1;
            As[nxt][lk + 0][lr] = a.x; As[nxt][lk + 1][lr] = a.y;
            As[nxt][lk + 2][lr] = a.z; As[nxt][lk + 3][lr] = a.w;
            Bs[nxt][lk + 0][lr] = b.x; Bs[nxt][lk + 1][lr] = b.y;
            Bs[nxt][lk + 2][lr] = b.z; Bs[nxt][lk + 3][lr] = b.w;
            __syncthreads();
            cur = nxt;
        }
    }

    float bias[8];
#pragma unroll
    for (int j = 0; j < 8; j++) bias[j] = bih[n0 + tx * 8 + j];

    float* gout = g_gi + (size_t)dir * B_ * S_ * G3_;
#pragma unroll
    for (int i = 0; i < 8; i++) {
        const size_t row = (size_t)(m0 + ty * 8 + i);
        float2 p0 = unpack2(acc2[i][0]);
        float2 p1 = unpack2(acc2[i][1]);
        float2 p2 = unpack2(acc2[i][2]);
        float2 p3 = unpack2(acc2[i][3]);
        float4 o0, o1;
        o0.x = p0.x + bias[0]; o0.y = p0.y + bias[1];
        o0.z = p1.x + bias[2]; o0.w = p1.y + bias[3];
        o1.x = p2.x + bias[4]; o1.y = p2.y + bias[5];
        o1.z = p3.x + bias[6]; o1.w = p3.y + bias[7];
        *(float4*)(gout + row * G3_ + n0 + tx * 8)     = o0;
        *(float4*)(gout + row * G3_ + n0 + tx * 8 + 4) = o1;
    }
}

// ---------------------------------------------------------------------------
// Kernel 2: GRU recurrence, both directions.
// Cluster of 4 CTAs = one (dir, batch-pair). CTA rank owns hidden units
// [rank*64, rank*64+64): 192 w_hh rows in registers (as f32x2 pairs).
// h double-buffered in SMEM, replicated cluster-wide via st.shared::cluster.
// Per-step sync: __syncthreads + 4x mbarrier.arrive.release.cluster +
// try_wait.parity.acquire.cluster (cheaper than barrier.cluster).
// ---------------------------------------------------------------------------
__global__ void __cluster_dims__(4, 1, 1) __launch_bounds__(256, 1)
rnn_rec(const float* __restrict__ whhf, const float* __restrict__ whhb,
        const float* __restrict__ bhhf, const float* __restrict__ bhhb,
        const float* __restrict__ V, float* __restrict__ out,
        int cl, int T)
{
    __shared__ __align__(16) float hbuf[2][2][256];   // [phase][batch][hidden]
    __shared__ __align__(8) unsigned long long mbar;

    const int tid = threadIdx.x;
    const int jl  = tid >> 2;
    const int ks  = tid & 3;
    unsigned rank;
    asm("mov.u32 %0, %%cluster_ctarank;" : "=r"(rank));
    const int j   = (int)rank * 64 + jl;
    const int dir = blockIdx.z;
    const int b0  = blockIdx.y * 2;

    const float* __restrict__ WHH = dir ? whhb : whhf;
    const float* __restrict__ BHH = dir ? bhhb : bhhf;

    // Register-resident weights as f32x2 pairs; chunk order XOR-swizzled by ks
    // so the four K-slice lanes of a quad read disjoint SMEM bank groups.
    unsigned long long wr2[32], wz2[32], wn2[32];
    {
        const float* pr = WHH + (size_t)(      j) * 256 + ks * 64;
        const float* pz = WHH + (size_t)(256 + j) * 256 + ks * 64;
        const float* pn = WHH + (size_t)(512 + j) * 256 + ks * 64;
#pragma unroll
        for (int i = 0; i < 16; i++) {
            const int ci = (i ^ (ks << 1)) & 15;
            ulonglong2 q;
            q = *(const ulonglong2*)(pr + ci * 4);
            wr2[2*i] = q.x; wr2[2*i+1] = q.y;
            q = *(const ulonglong2*)(pz + ci * 4);
            wz2[2*i] = q.x; wz2[2*i+1] = q.y;
            q = *(const ulonglong2*)(pn + ci * 4);
            wn2[2*i] = q.x; wn2[2*i+1] = q.y;
        }
    }
    const float br = BHH[j], bz = BHH[256 + j], bn = BHH[512 + j];

    const uint32_t hb  = smem_u32(&hbuf[0][0][0]);
    const uint32_t mba = smem_u32(&mbar);

    // init: zero h phase 0, init mbarrier (4 arrivals = one per cluster CTA)
    if (tid < 128) ((float4*)&hbuf[0][0][0])[tid] = make_float4(0.f, 0.f, 0.f, 0.f);
    if (tid == 0)
        asm volatile("mbarrier.init.shared.b64 [%0], %1;"
                     :: "r"(mba), "r"(4) : "memory");
    __syncthreads();
    asm volatile("barrier.cluster.arrive.aligned;" ::: "memory");
    asm volatile("barrier.cluster.wait.aligned;"   ::: "memory");

    const int s0 = dir ? (S_ - 1) : 0;
    const ptrdiff_t gstep = dir ? -(ptrdiff_t)G3_ : (ptrdiff_t)G3_;
    const ptrdiff_t vstep = dir ? -(ptrdiff_t)256 : (ptrdiff_t)256;
    const int bb = ks & 1;   // gate-owner lanes: ks==0 -> batch0, ks==1 -> batch1

    const float* gi_my = g_gi + ((size_t)dir * B_ + b0 + bb) * S_ * G3_
                              + (size_t)s0 * G3_ + j;
    const float* v_my  = V + ((size_t)(b0 + bb) * S_ + s0) * 256 + j;
    float* o_my        = out + (size_t)(b0 + bb) * T * 512 + (size_t)dir * 256 + j;

    float g_r = 0.f, g_z = 0.f, g_n = 0.f, vv = 0.f, hp = 0.f;

    for (int step = 0; step < S_; ++step) {
        const int p = step & 1;
        const float* hs = &hbuf[p][0][0];

        // early loads (gate-owner lanes only) — hide under the FMA phase
        if (ks < 2) {
            g_r = gi_my[0];
            g_z = gi_my[256];
            g_n = gi_my[512];
            vv  = v_my[0];
            hp  = hs[bb * 256 + j];
        }

        // --- gh partials: 2 batches x 3 gates x 64 K, packed f32x2 ---
        unsigned long long ar0 = 0, az0 = 0, an0 = 0;
        unsigned long long ar1 = 0, az1 = 0, an1 = 0;
        const float* h0 = hs + ks * 64;
        const float* h1 = hs + 256 + ks * 64;
#pragma unroll
        for (int i = 0; i < 16; i++) {
            const int ci = (i ^ (ks << 1)) & 15;
            ulonglong2 hv = *(const ulonglong2*)(h0 + 4 * ci);
            ffma2(ar0, wr2[2*i], hv.x); ffma2(ar0, wr2[2*i+1], hv.y);
            ffma2(az0, wz2[2*i], hv.x); ffma2(az0, wz2[2*i+1], hv.y);
            ffma2(an0, wn2[2*i], hv.x); ffma2(an0, wn2[2*i+1], hv.y);
        }
#pragma unroll
        for (int i = 0; i < 16; i++) {
            const int ci = (i ^ (ks << 1)) & 15;
            ulonglong2 hv = *(const ulonglong2*)(h1 + 4 * ci);
            ffma2(ar1, wr2[2*i], hv.x); ffma2(ar1, wr2[2*i+1], hv.y);
            ffma2(az1, wz2[2*i], hv.x); ffma2(az1, wz2[2*i+1], hv.y);
            ffma2(an1, wn2[2*i], hv.x); ffma2(an1, wn2[2*i+1], hv.y);
        }

        // collapse packed halves, then quad butterfly reduce
        float2 t;
        t = unpack2(ar0); float r0 = t.x + t.y;
        t = unpack2(az0); float z0 = t.x + t.y;
        t = unpack2(an0); float n0v = t.x + t.y;
        t = unpack2(ar1); float r1 = t.x + t.y;
        t = unpack2(az1); float z1 = t.x + t.y;
        t = unpack2(an1); float n1v = t.x + t.y;

        r0  += __shfl_xor_sync(0xffffffffu, r0, 1, 4);
        r0  += __shfl_xor_sync(0xffffffffu, r0, 2, 4);
        z0  += __shfl_xor_sync(0xffffffffu, z0, 1, 4);
        z0  += __shfl_xor_sync(0xffffffffu, z0, 2, 4);
        n0v += __shfl_xor_sync(0xffffffffu, n0v, 1, 4);
        n0v += __shfl_xor_sync(0xffffffffu, n0v, 2, 4);
        r1  += __shfl_xor_sync(0xffffffffu, r1, 1, 4);
        r1  += __shfl_xor_sync(0xffffffffu, r1, 2, 4);
        z1  += __shfl_xor_sync(0xffffffffu, z1, 1, 4);
        z1  += __shfl_xor_sync(0xffffffffu, z1, 2, 4);
        n1v += __shfl_xor_sync(0xffffffffu, n1v, 1, 4);
        n1v += __shfl_xor_sync(0xffffffffu, n1v, 2, 4);

        if (ks < 2) {
            const float ar = bb ? r1 : r0;
            const float az = bb ? z1 : z0;
            const float an = bb ? n1v : n0v;

            const float r  = fast_sig(g_r + ar + br);
            const float z  = fast_sig(g_z + az + bz);
            const float n  = fast_tanh(g_n + r * (an + bn));
            const float hn = (1.f - z) * n + z * hp;

            // replicate h' into every cluster CTA's next-phase buffer
            const uint32_t la = hb + 4u * (uint32_t)(((p ^ 1) * 2 + bb) * 256 + j);
#pragma unroll
            for (int rdst = 0; rdst < 4; rdst++) {
                uint32_t ra;
                asm("mapa.shared::cluster.u32 %0, %1, %2;"
                    : "=r"(ra) : "r"(la), "r"(rdst));
                asm volatile("st.shared::cluster.f32 [%0], %1;"
                             :: "r"(ra), "f"(hn) : "memory");
            }

            if ((unsigned)(step - cl) < (unsigned)T)
                o_my[(size_t)(step - cl) * 512] = hn + vv;
        }

        gi_my += gstep;
        v_my  += vstep;

        // --- cluster step sync: bar.sync -> 4x remote arrive -> parity wait ---
        __syncthreads();
        if (tid < 4) {
            uint32_t ra;
            asm("mapa.shared::cluster.u32 %0, %1, %2;"
                : "=r"(ra) : "r"(mba), "r"(tid));
            asm volatile("mbarrier.arrive.release.cluster.shared::cluster.b64 _, [%0];"
                         :: "r"(ra) : "memory");
        }
        {
            const uint32_t par = (uint32_t)(step & 1);
            asm volatile(
                "{\n\t"
                ".reg .pred P;\n"
                "W%=:\n\t"
                "mbarrier.try_wait.parity.acquire.cluster.shared::cta.b64 P, [%0], %1, 0x989680;\n\t"
                "@!P bra W%=;\n\t"
                "}"
                :: "r"(mba), "r"(par) : "memory");
        }
    }
}

// ---------------------------------------------------------------------------
extern "C" void kernel_launch(void* const* d_in, const int* in_sizes, int n_in,
                              void* d_out, int out_size)
{
    const float* V    = (const float*)d_in[0];
    const float* wihf = (const float*)d_in[1];
    const float* whhf = (const float*)d_in[2];
    const float* bihf = (const float*)d_in[3];
    const float* bhhf = (const float*)d_in[4];
    const float* wihb = (const float*)d_in[5];
    const float* whhb = (const float*)d_in[6];
    const float* bihb = (const float*)d_in[7];
    const float* bhhb = (const float*)d_in[8];
    float* out = (float*)d_out;

    const int T  = out_size / (B_ * 512);   // 2028
    const int cl = (S_ - T) / 2;            // 10

    dim3 gg((B_ * S_) / 128, G3_ / 128, 2); // (512, 6, 2)
    gi_gemm<<<gg, 256>>>(V, wihf, wihb, bihf, bihb);

    dim3 gr(4, B_ / 2, 2);                  // (4, 16, 2) — clusters of 4
    rnn_rec<<<gr, 256>>>(whhf, whhb, bhhf, bhhb, V, out, cl, T);
}

// round 7
// speedup vs baseline: 1.0950x; 1.0950x over previous
#include <cuda_runtime.h>
#include <cuda_bf16.h>
#include <cstdint>
#include <cstddef>

#define B_   32
#define S_   2048
#define D_   256
#define G3_  768

// gi scratch: [dir][b][s][768]  (402 MB, fully rewritten every call)
__device__ float g_gi[(size_t)2 * B_ * S_ * G3_];

// ---------------------------------------------------------------------------
// helpers
// ---------------------------------------------------------------------------
__device__ __forceinline__ float2 unpack2(unsigned long long v) {
    float2 f;
    asm("mov.b64 {%0,%1}, %2;" : "=f"(f.x), "=f"(f.y) : "l"(v));
    return f;
}
__device__ __forceinline__ void ffma2(unsigned long long& d,
                                      unsigned long long a,
                                      unsigned long long b) {
    asm("fma.rn.f32x2 %0, %1, %2, %0;" : "+l"(d) : "l"(a), "l"(b));
}
__device__ __forceinline__ uint32_t smem_u32(const void* p) {
    uint32_t a;
    asm("{ .reg .u64 t; cvta.to.shared.u64 t, %1; cvt.u32.u64 %0, t; }"
        : "=r"(a) : "l"(p));
    return a;
}
__device__ __forceinline__ float fast_sig(float x) {
    return __fdividef(1.f, 1.f + __expf(-x));
}
__device__ __forceinline__ float fast_tanh(float x) {
    return __fdividef(2.f, 1.f + __expf(-2.f * x)) - 1.f;
}

// ---------------------------------------------------------------------------
// Kernel 1: gi[dir][m][n] = V[m][:] . W_ih(dir)[n][:] + b_ih[n]
// M = 65536, N = 768, K = 256. 128x128x8 fp32 SGEMM (scalar FFMA, R4-proven).
// ---------------------------------------------------------------------------
__global__ __launch_bounds__(256, 2) void gi_gemm(
    const float* __restrict__ V,
    const float* __restrict__ Wf, const float* __restrict__ Wb,
    const float* __restrict__ bf, const float* __restrict__ bb)
{
    const int dir = blockIdx.z;
    const float* __restrict__ W   = dir ? Wb : Wf;
    const float* __restrict__ bih = dir ? bb : bf;
    const int m0 = blockIdx.x * 128;
    const int n0 = blockIdx.y * 128;

    __shared__ float As[2][8][132];
    __shared__ float Bs[2][8][132];

    const int tid = threadIdx.x;
    const int lr  = tid >> 1;
    const int lk  = (tid & 1) * 4;

    const float* aptr = V + (size_t)(m0 + lr) * 256 + lk;
    const float* bptr = W + (size_t)(n0 + lr) * 256 + lk;

    const int tx = tid & 15;
    const int ty = tid >> 4;

    float acc[8][8];
#pragma unroll
    for (int i = 0; i < 8; i++)
#pragma unroll
        for (int j = 0; j < 8; j++) acc[i][j] = 0.f;

    float4 a = *(const float4*)aptr;
    float4 b = *(const float4*)bptr;
    As[0][lk + 0][lr] = a.x; As[0][lk + 1][lr] = a.y;
    As[0][lk + 2][lr] = a.z; As[0][lk + 3][lr] = a.w;
    Bs[0][lk + 0][lr] = b.x; Bs[0][lk + 1][lr] = b.y;
    Bs[0][lk + 2][lr] = b.z; Bs[0][lk + 3][lr] = b.w;
    __syncthreads();

    int cur = 0;
    for (int kt = 0; kt < 32; kt++) {
        if (kt < 31) {
            a = *(const float4*)(aptr + (kt + 1) * 8);
            b = *(const float4*)(bptr + (kt + 1) * 8);
        }
#pragma unroll
        for (int k = 0; k < 8; k++) {
            float4 a0 = *(const float4*)&As[cur][k][ty * 8];
            float4 a1 = *(const float4*)&As[cur][k][ty * 8 + 4];
            float4 b0 = *(const float4*)&Bs[cur][k][tx * 8];
            float4 b1 = *(const float4*)&Bs[cur][k][tx * 8 + 4];
            float av[8] = {a0.x, a0.y, a0.z, a0.w, a1.x, a1.y, a1.z, a1.w};
            float bv[8] = {b0.x, b0.y, b0.z, b0.w, b1.x, b1.y, b1.z, b1.w};
#pragma unroll
            for (int i = 0; i < 8; i++)
#pragma unroll
                for (int j = 0; j < 8; j++)
                    acc[i][j] = fmaf(av[i], bv[j], acc[i][j]);
        }
        if (kt < 31) {
            const int nxt = cur ^ 1;
            As[nxt][lk + 0][lr] = a.x; As[nxt][lk + 1][lr] = a.y;
            As[nxt][lk + 2][lr] = a.z; As[nxt][lk + 3][lr] = a.w;
            Bs[nxt][lk + 0][lr] = b.x; Bs[nxt][lk + 1][lr] = b.y;
            Bs[nxt][lk + 2][lr] = b.z; Bs[nxt][lk + 3][lr] = b.w;
            __syncthreads();
            cur = nxt;
        }
    }

    float bias[8];
#pragma unroll
    for (int j = 0; j < 8; j++) bias[j] = bih[n0 + tx * 8 + j];

    float* gout = g_gi + (size_t)dir * B_ * S_ * G3_;
#pragma unroll
    for (int i = 0; i < 8; i++) {
        const size_t row = (size_t)(m0 + ty * 8 + i);
        float4 o0, o1;
        o0.x = acc[i][0] + bias[0]; o0.y = acc[i][1] + bias[1];
        o0.z = acc[i][2] + bias[2]; o0.w = acc[i][3] + bias[3];
        o1.x = acc[i][4] + bias[4]; o1.y = acc[i][5] + bias[5];
        o1.z = acc[i][6] + bias[6]; o1.w = acc[i][7] + bias[7];
        *(float4*)(gout + row * G3_ + n0 + tx * 8)     = o0;
        *(float4*)(gout + row * G3_ + n0 + tx * 8 + 4) = o1;
    }
}

// ---------------------------------------------------------------------------
// Kernel 2: GRU recurrence. Cluster of 4 CTAs = one (dir, batch-pair).
// CTA rank owns hidden units [rank*64, rank*64+64).
//   w_r, w_z : register-resident f32x2 pairs (128 regs)  -> NO spills
//   w_n      : streamed from SMEM each step (64 KB slice, pad-260 rows,
//              conflict-free 4-wavefront LDS.128)
// h double-buffered in dynamic SMEM, replicated via st.shared::cluster;
// per-step sync = __syncthreads + 4x mbarrier arrive.release.cluster + wait.
// Dynamic SMEM layout (floats): wn[64*260] | hbuf[2][2][256] | mbar(u64)
// ---------------------------------------------------------------------------
#define WN_STRIDE 260
#define SM_WN     0
#define SM_HBUF   (64 * WN_STRIDE)             // 16640 floats
#define SM_MBAR   (SM_HBUF + 1024)             // 17664 floats
#define SM_FLOATS (SM_MBAR + 4)                // +16B for mbar
#define SM_BYTES  (SM_FLOATS * 4)

__global__ void __cluster_dims__(4, 1, 1) __launch_bounds__(256, 1)
rnn_rec(const float* __restrict__ whhf, const float* __restrict__ whhb,
        const float* __restrict__ bhhf, const float* __restrict__ bhhb,
        const float* __restrict__ V, float* __restrict__ out,
        int cl, int T)
{
    extern __shared__ __align__(16) float smem[];
    float* wn_s = smem + SM_WN;
    float* hbuf = smem + SM_HBUF;              // [phase][batch][256]

    const int tid = threadIdx.x;
    const int jl  = tid >> 2;
    const int ks  = tid & 3;
    unsigned rank;
    asm("mov.u32 %0, %%cluster_ctarank;" : "=r"(rank));
    const int j   = (int)rank * 64 + jl;
    const int dir = blockIdx.z;
    const int b0  = blockIdx.y * 2;

    const float* __restrict__ WHH = dir ? whhb : whhf;
    const float* __restrict__ BHH = dir ? bhhb : bhhf;

    // w_r, w_z in registers as f32x2 pairs, chunk order XOR-swizzled by ks.
    unsigned long long wr2[32], wz2[32];
    {
        const float* pr = WHH + (size_t)(      j) * 256 + ks * 64;
        const float* pz = WHH + (size_t)(256 + j) * 256 + ks * 64;
#pragma unroll
        for (int i = 0; i < 16; i++) {
            const int ci = (i ^ (ks << 1)) & 15;
            ulonglong2 q;
            q = *(const ulonglong2*)(pr + ci * 4);
            wr2[2*i] = q.x; wr2[2*i+1] = q.y;
            q = *(const ulonglong2*)(pz + ci * 4);
            wz2[2*i] = q.x; wz2[2*i+1] = q.y;
        }
    }
    const float br = BHH[j], bz = BHH[256 + j], bn = BHH[512 + j];

    // w_n slice -> SMEM (coalesced float4), padded rows.
    {
        const float* src = WHH + (size_t)(512 + (int)rank * 64) * 256;
        for (int idx = tid; idx < 64 * 64; idx += 256) {
            const int u  = idx >> 6;
            const int c4 = idx & 63;
            float4 q = *(const float4*)(src + (size_t)u * 256 + c4 * 4);
            *(float4*)(wn_s + u * WN_STRIDE + c4 * 4) = q;
        }
    }

    const uint32_t hb  = smem_u32(hbuf);
    const uint32_t mba = smem_u32(smem + SM_MBAR);

    if (tid < 128) ((float4*)hbuf)[tid] = make_float4(0.f, 0.f, 0.f, 0.f);
    if (tid == 0)
        asm volatile("mbarrier.init.shared.b64 [%0], %1;"
                     :: "r"(mba), "r"(4) : "memory");
    __syncthreads();
    asm volatile("barrier.cluster.arrive.aligned;" ::: "memory");
    asm volatile("barrier.cluster.wait.aligned;"   ::: "memory");

    const int s0 = dir ? (S_ - 1) : 0;
    const ptrdiff_t gstep = dir ? -(ptrdiff_t)G3_ : (ptrdiff_t)G3_;
    const ptrdiff_t vstep = dir ? -(ptrdiff_t)256 : (ptrdiff_t)256;
    const int bb = ks & 1;   // gate-owner lanes: ks==0 -> batch0, ks==1 -> batch1

    const float* gi_my = g_gi + ((size_t)dir * B_ + b0 + bb) * S_ * G3_
                              + (size_t)s0 * G3_ + j;
    const float* v_my  = V + ((size_t)(b0 + bb) * S_ + s0) * 256 + j;
    float* o_my        = out + (size_t)(b0 + bb) * T * 512 + (size_t)dir * 256 + j;

    const float* wn_row = wn_s + jl * WN_STRIDE + ks * 64;

    float g_r = 0.f, g_z = 0.f, g_n = 0.f, vv = 0.f, hp = 0.f;

    for (int step = 0; step < S_; ++step) {
        const int p = step & 1;
        const float* hs = hbuf + p * 512;

        if (ks < 2) {
            g_r = gi_my[0];
            g_z = gi_my[256];
            g_n = gi_my[512];
            vv  = v_my[0];
            hp  = hs[bb * 256 + j];
        }

        unsigned long long ar0 = 0, az0 = 0, an0 = 0;
        unsigned long long ar1 = 0, az1 = 0, an1 = 0;
        const float* h0 = hs + ks * 64;
        const float* h1 = hs + 256 + ks * 64;
#pragma unroll
        for (int i = 0; i < 16; i++) {
            const int ci = (i ^ (ks << 1)) & 15;
            ulonglong2 hv0 = *(const ulonglong2*)(h0 + 4 * ci);
            ulonglong2 hv1 = *(const ulonglong2*)(h1 + 4 * ci);
            ulonglong2 wn  = *(const ulonglong2*)(wn_row + 4 * ci);
            ffma2(ar0, wr2[2*i],   hv0.x); ffma2(ar0, wr2[2*i+1], hv0.y);
            ffma2(az0, wz2[2*i],   hv0.x); ffma2(az0, wz2[2*i+1], hv0.y);
            ffma2(an0, wn.x,       hv0.x); ffma2(an0, wn.y,       hv0.y);
            ffma2(ar1, wr2[2*i],   hv1.x); ffma2(ar1, wr2[2*i+1], hv1.y);
            ffma2(az1, wz2[2*i],   hv1.x); ffma2(az1, wz2[2*i+1], hv1.y);
            ffma2(an1, wn.x,       hv1.x); ffma2(an1, wn.y,       hv1.y);
        }

        float2 t;
        t = unpack2(ar0); float r0  = t.x + t.y;
        t = unpack2(az0); float z0  = t.x + t.y;
        t = unpack2(an0); float n0v = t.x + t.y;
        t = unpack2(ar1); float r1  = t.x + t.y;
        t = unpack2(az1); float z1  = t.x + t.y;
        t = unpack2(an1); float n1v = t.x + t.y;

        r0  += __shfl_xor_sync(0xffffffffu, r0, 1, 4);
        r0  += __shfl_xor_sync(0xffffffffu, r0, 2, 4);
        z0  += __shfl_xor_sync(0xffffffffu, z0, 1, 4);
        z0  += __shfl_xor_sync(0xffffffffu, z0, 2, 4);
        n0v += __shfl_xor_sync(0xffffffffu, n0v, 1, 4);
        n0v += __shfl_xor_sync(0xffffffffu, n0v, 2, 4);
        r1  += __shfl_xor_sync(0xffffffffu, r1, 1, 4);
        r1  += __shfl_xor_sync(0xffffffffu, r1, 2, 4);
        z1  += __shfl_xor_sync(0xffffffffu, z1, 1, 4);
        z1  += __shfl_xor_sync(0xffffffffu, z1, 2, 4);
        n1v += __shfl_xor_sync(0xffffffffu, n1v, 1, 4);
        n1v += __shfl_xor_sync(0xffffffffu, n1v, 2, 4);

        if (ks < 2) {
            const float ar = bb ? r1  : r0;
            const float az = bb ? z1  : z0;
            const float an = bb ? n1v : n0v;

            const float r  = fast_sig(g_r + ar + br);
            const float z  = fast_sig(g_z + az + bz);
            const float n  = fast_tanh(g_n + r * (an + bn));
            const float hn = (1.f - z) * n + z * hp;

            const uint32_t la = hb + 4u * (uint32_t)(((p ^ 1) * 2 + bb) * 256 + j);
#pragma unroll
            for (int rdst = 0; rdst < 4; rdst++) {
                uint32_t ra;
                asm("mapa.shared::cluster.u32 %0, %1, %2;"
                    : "=r"(ra) : "r"(la), "r"(rdst));
                asm volatile("st.shared::cluster.f32 [%0], %1;"
                             :: "r"(ra), "f"(hn) : "memory");
            }

            if ((unsigned)(step - cl) < (unsigned)T)
                o_my[(size_t)(step - cl) * 512] = hn + vv;
        }

        gi_my += gstep;
        v_my  += vstep;

        __syncthreads();
        if (tid < 4) {
            uint32_t ra;
            asm("mapa.shared::cluster.u32 %0, %1, %2;"
                : "=r"(ra) : "r"(mba), "r"(tid));
            asm volatile("mbarrier.arrive.release.cluster.shared::cluster.b64 _, [%0];"
                         :: "r"(ra) : "memory");
        }
        {
            const uint32_t par = (uint32_t)(step & 1);
            asm volatile(
                "{\n\t"
                ".reg .pred P;\n"
                "W%=:\n\t"
                "mbarrier.try_wait.parity.acquire.cluster.shared::cta.b64 P, [%0], %1, 0x989680;\n\t"
                "@!P bra W%=;\n\t"
                "}"
                :: "r"(mba), "r"(par) : "memory");
        }
    }
}

// ---------------------------------------------------------------------------
extern "C" void kernel_launch(void* const* d_in, const int* in_sizes, int n_in,
                              void* d_out, int out_size)
{
    const float* V    = (const float*)d_in[0];
    const float* wihf = (const float*)d_in[1];
    const float* whhf = (const float*)d_in[2];
    const float* bihf = (const float*)d_in[3];
    const float* bhhf = (const float*)d_in[4];
    const float* wihb = (const float*)d_in[5];
    const float* whhb = (const float*)d_in[6];
    const float* bihb = (const float*)d_in[7];
    const float* bhhb = (const float*)d_in[8];
    float* out = (float*)d_out;

    const int T  = out_size / (B_ * 512);   // 2028
    const int cl = (S_ - T) / 2;            // 10

    dim3 gg((B_ * S_) / 128, G3_ / 128, 2); // (512, 6, 2)
    gi_gemm<<<gg, 256>>>(V, wihf, wihb, bihf, bihb);

    cudaFuncSetAttribute(rnn_rec, cudaFuncAttributeMaxDynamicSharedMemorySize,
                         SM_BYTES);
    dim3 gr(4, B_ / 2, 2);                  // (4, 16, 2) — clusters of 4
    rnn_rec<<<gr, 256, SM_BYTES>>>(whhf, whhb, bhhf, bhhb, V, out, cl, T);
}